// round 11
// baseline (speedup 1.0000x reference)
#include <cuda_runtime.h>
#include <cstdint>

// GraphReversePool: out[b, v] = x[b, v2c[v]]
//   x   : [BATCH, N_CLUSTERS] fp32   (d_in[0])
//   v2c : [VERTICES] int32           (d_in[1])
//   out : [BATCH, VERTICES] fp32
//
// R10: R5 macro-shape (grid=batch, 1 row/CTA, cp.async.bulk staging,
// 2 CTAs/SM, 2-quad gather, .cs stores) + u16 index compression:
// n_clusters < 65536, so a per-launch prep kernel packs v2c into a
// __device__ u16 array. Gather loads 8 indices per LDG.128 -> index LDG
// work and v2c L2 traffic halve.

#define BLOCK_THREADS 1024
#define MAX_VERTICES_U16 131072

__device__ __align__(16) unsigned short g_v2c16[MAX_VERTICES_U16];

__device__ __forceinline__ uint32_t smem_u32(const void* p) {
    return (uint32_t)__cvta_generic_to_shared(p);
}

__global__ void pack_v2c_kernel(const int* __restrict__ v2c, int n)
{
    // pack 8 int32 -> 8 u16 (one uint4 store) per thread
    const int n8 = n >> 3;
    int i = blockIdx.x * blockDim.x + threadIdx.x;
    if (i < n8) {
        const int4 a = reinterpret_cast<const int4*>(v2c)[2 * i];
        const int4 b = reinterpret_cast<const int4*>(v2c)[2 * i + 1];
        uint4 p;
        p.x = (uint32_t)(a.x & 0xFFFF) | ((uint32_t)a.y << 16);
        p.y = (uint32_t)(a.z & 0xFFFF) | ((uint32_t)a.w << 16);
        p.z = (uint32_t)(b.x & 0xFFFF) | ((uint32_t)b.y << 16);
        p.w = (uint32_t)(b.z & 0xFFFF) | ((uint32_t)b.w << 16);
        reinterpret_cast<uint4*>(g_v2c16)[i] = p;
    }
    // scalar tail
    const int t = (n8 << 3) + i;
    if (i < 8 && t < n) {
        g_v2c16[t] = (unsigned short)v2c[t];
    }
}

__global__ __launch_bounds__(BLOCK_THREADS, 2)
void graph_reverse_pool_kernel(const float* __restrict__ x,
                               const int*   __restrict__ v2c,
                               float*       __restrict__ out,
                               int batch, int n_clusters, int n_vertices,
                               int use_u16)
{
    extern __shared__ __align__(16) unsigned char smem_raw[];
    float* srow = reinterpret_cast<float*>(smem_raw);

    const int b = blockIdx.x;

    const int row_bytes = n_clusters * 4;
    const int mbar_off  = (row_bytes + 15) & ~15;
    uint64_t* mbar = reinterpret_cast<uint64_t*>(smem_raw + mbar_off);
    const uint32_t mbar_addr = smem_u32(mbar);

    const float* __restrict__ xrow = x + (size_t)b * n_clusters;

    // ---- Stage x row into smem with one bulk DMA ----
    const bool can_bulk = ((row_bytes & 15) == 0) &&
                          ((((uintptr_t)xrow) & 15) == 0);
    if (can_bulk) {
        if (threadIdx.x == 0) {
            asm volatile("mbarrier.init.shared.b64 [%0], 1;"
                         :: "r"(mbar_addr) : "memory");
            asm volatile("fence.proxy.async.shared::cta;" ::: "memory");
        }
        __syncthreads();
        if (threadIdx.x == 0) {
            asm volatile("mbarrier.arrive.expect_tx.shared.b64 _, [%0], %1;"
                         :: "r"(mbar_addr), "r"((uint32_t)row_bytes) : "memory");
            asm volatile("cp.async.bulk.shared::cta.global.mbarrier::complete_tx::bytes "
                         "[%0], [%1], %2, [%3];"
                         :: "r"(smem_u32(srow)), "l"(xrow),
                            "r"((uint32_t)row_bytes), "r"(mbar_addr)
                         : "memory");
        }
        uint32_t done = 0;
        while (!done) {
            asm volatile(
                "{\n\t.reg .pred p;\n\t"
                "mbarrier.try_wait.parity.acquire.cta.shared::cta.b64 p, [%1], 0, 0x989680;\n\t"
                "selp.b32 %0, 1, 0, p;\n\t}"
                : "=r"(done) : "r"(mbar_addr) : "memory");
        }
    } else {
        for (int i = threadIdx.x; i < n_clusters; i += BLOCK_THREADS)
            srow[i] = xrow[i];
        __syncthreads();
    }

    float4* __restrict__ o = reinterpret_cast<float4*>(out + (size_t)b * n_vertices);
    const int S = BLOCK_THREADS;

    if (use_u16) {
        // ---- Gather: 1x LDG.128 (8 u16 idx) -> 8x LDS -> 2x STG.128.cs ----
        const uint4* __restrict__ idx8 = reinterpret_cast<const uint4*>(g_v2c16);
        const int nv8 = n_vertices >> 3;           // 12500 octs (exact for 100000)

        int v = threadIdx.x;
        if (v < nv8) {
            uint4 w = idx8[v];
            int vn = v + S;
            while (vn < nv8) {
                const uint4 wn = idx8[vn];         // prefetch next 8 indices
                float4 a0, a1;
                a0.x = srow[w.x & 0xFFFF]; a0.y = srow[w.x >> 16];
                a0.z = srow[w.y & 0xFFFF]; a0.w = srow[w.y >> 16];
                a1.x = srow[w.z & 0xFFFF]; a1.y = srow[w.z >> 16];
                a1.z = srow[w.w & 0xFFFF]; a1.w = srow[w.w >> 16];
                __stcs(&o[2 * v],     a0);
                __stcs(&o[2 * v + 1], a1);
                v = vn; vn += S;
                w = wn;
            }
            float4 a0, a1;
            a0.x = srow[w.x & 0xFFFF]; a0.y = srow[w.x >> 16];
            a0.z = srow[w.y & 0xFFFF]; a0.w = srow[w.y >> 16];
            a1.x = srow[w.z & 0xFFFF]; a1.y = srow[w.z >> 16];
            a1.z = srow[w.w & 0xFFFF]; a1.w = srow[w.w >> 16];
            __stcs(&o[2 * v],     a0);
            __stcs(&o[2 * v + 1], a1);
        }
        // scalar tail over [nv8*8, n_vertices) (dead for 100000)
        for (int t = (nv8 << 3) + threadIdx.x; t < n_vertices; t += S) {
            out[(size_t)b * n_vertices + t] = srow[v2c[t]];
        }
    } else {
        // fallback: int32 index path (n_clusters >= 65536 or odd shapes)
        const int4* __restrict__ v2c4 = reinterpret_cast<const int4*>(v2c);
        const int nv4 = n_vertices >> 2;
        int v = threadIdx.x;
        while (v + S < nv4) {
            const int4 c0 = v2c4[v];
            const int4 c1 = v2c4[v + S];
            float4 a0, a1;
            a0.x = srow[c0.x]; a0.y = srow[c0.y]; a0.z = srow[c0.z]; a0.w = srow[c0.w];
            a1.x = srow[c1.x]; a1.y = srow[c1.y]; a1.z = srow[c1.z]; a1.w = srow[c1.w];
            __stcs(&o[v],     a0);
            __stcs(&o[v + S], a1);
            v += 2 * S;
        }
        if (v < nv4) {
            const int4 c = v2c4[v];
            float4 a;
            a.x = srow[c.x]; a.y = srow[c.y]; a.z = srow[c.z]; a.w = srow[c.w];
            __stcs(&o[v], a);
        }
        for (int t = (nv4 << 2) + threadIdx.x; t < n_vertices; t += S) {
            out[(size_t)b * n_vertices + t] = srow[v2c[t]];
        }
    }
}

extern "C" void kernel_launch(void* const* d_in, const int* in_sizes, int n_in,
                              void* d_out, int out_size)
{
    const float* x   = (const float*)d_in[0];
    const int*   v2c = (const int*)  d_in[1];
    float*       out = (float*)d_out;

    const int n_vertices = in_sizes[1];                  // 100000
    const int batch      = out_size / n_vertices;        // 1024
    const int n_clusters = in_sizes[0] / batch;          // 25000

    const int row_bytes  = n_clusters * (int)sizeof(float);      // 100000
    const int smem_bytes = ((row_bytes + 15) & ~15) + 16;        // row + mbarrier

    static bool attr_set = false;
    if (!attr_set) {
        cudaFuncSetAttribute(graph_reverse_pool_kernel,
                             cudaFuncAttributeMaxDynamicSharedMemorySize,
                             smem_bytes);
        attr_set = true;
    }

    const int use_u16 = (n_clusters <= 65535) &&
                        (n_vertices <= MAX_VERTICES_U16) &&
                        ((n_vertices & 7) == 0 || n_vertices >= 8);

    if (use_u16) {
        const int n8 = (n_vertices + 7) / 8;
        pack_v2c_kernel<<<(n8 + 255) / 256, 256>>>(v2c, n_vertices);
    }

    graph_reverse_pool_kernel<<<batch, BLOCK_THREADS, smem_bytes>>>(
        x, v2c, out, batch, n_clusters, n_vertices, use_u16 ? 1 : 0);
}

// round 12
// speedup vs baseline: 1.3834x; 1.3834x over previous
#include <cuda_runtime.h>
#include <cstdint>

// GraphReversePool: out[b, v] = x[b, v2c[v]]
//   x   : [BATCH, N_CLUSTERS] fp32   (d_in[0])
//   v2c : [VERTICES] int32           (d_in[1])
//   out : [BATCH, VERTICES] fp32
//
// R11: exact R5 schedule (grid=batch, 1 row/CTA, cp.async.bulk staging,
// 2 CTAs/SM, 2-quad gather with COALESCED stores, .cs) + u16 indices
// loaded as uint2 (LDG.64) per quad. Output mapping identical to R5
// (thread -> quads v, v+S), fixing R10's store-decoalescing bug while
// keeping the halved v2c traffic.

#define BLOCK_THREADS 1024
#define MAX_VERTICES_U16 131072

__device__ __align__(16) unsigned short g_v2c16[MAX_VERTICES_U16];

__device__ __forceinline__ uint32_t smem_u32(const void* p) {
    return (uint32_t)__cvta_generic_to_shared(p);
}

__global__ void pack_v2c_kernel(const int* __restrict__ v2c, int n)
{
    // pack 8 int32 -> 8 u16 (one uint4 store) per thread
    const int n8 = n >> 3;
    int i = blockIdx.x * blockDim.x + threadIdx.x;
    if (i < n8) {
        const int4 a = reinterpret_cast<const int4*>(v2c)[2 * i];
        const int4 b = reinterpret_cast<const int4*>(v2c)[2 * i + 1];
        uint4 p;
        p.x = (uint32_t)(a.x & 0xFFFF) | ((uint32_t)a.y << 16);
        p.y = (uint32_t)(a.z & 0xFFFF) | ((uint32_t)a.w << 16);
        p.z = (uint32_t)(b.x & 0xFFFF) | ((uint32_t)b.y << 16);
        p.w = (uint32_t)(b.z & 0xFFFF) | ((uint32_t)b.w << 16);
        reinterpret_cast<uint4*>(g_v2c16)[i] = p;
    }
    // scalar tail
    const int t = (n8 << 3) + i;
    if (i < 8 && t < n) {
        g_v2c16[t] = (unsigned short)v2c[t];
    }
}

__global__ __launch_bounds__(BLOCK_THREADS, 2)
void graph_reverse_pool_kernel(const float* __restrict__ x,
                               const int*   __restrict__ v2c,
                               float*       __restrict__ out,
                               int batch, int n_clusters, int n_vertices,
                               int use_u16)
{
    extern __shared__ __align__(16) unsigned char smem_raw[];
    float* srow = reinterpret_cast<float*>(smem_raw);

    const int b = blockIdx.x;

    const int row_bytes = n_clusters * 4;
    const int mbar_off  = (row_bytes + 15) & ~15;
    uint64_t* mbar = reinterpret_cast<uint64_t*>(smem_raw + mbar_off);
    const uint32_t mbar_addr = smem_u32(mbar);

    const float* __restrict__ xrow = x + (size_t)b * n_clusters;

    // ---- Stage x row into smem with one bulk DMA ----
    const bool can_bulk = ((row_bytes & 15) == 0) &&
                          ((((uintptr_t)xrow) & 15) == 0);
    if (can_bulk) {
        if (threadIdx.x == 0) {
            asm volatile("mbarrier.init.shared.b64 [%0], 1;"
                         :: "r"(mbar_addr) : "memory");
            asm volatile("fence.proxy.async.shared::cta;" ::: "memory");
        }
        __syncthreads();
        if (threadIdx.x == 0) {
            asm volatile("mbarrier.arrive.expect_tx.shared.b64 _, [%0], %1;"
                         :: "r"(mbar_addr), "r"((uint32_t)row_bytes) : "memory");
            asm volatile("cp.async.bulk.shared::cta.global.mbarrier::complete_tx::bytes "
                         "[%0], [%1], %2, [%3];"
                         :: "r"(smem_u32(srow)), "l"(xrow),
                            "r"((uint32_t)row_bytes), "r"(mbar_addr)
                         : "memory");
        }
        uint32_t done = 0;
        while (!done) {
            asm volatile(
                "{\n\t.reg .pred p;\n\t"
                "mbarrier.try_wait.parity.acquire.cta.shared::cta.b64 p, [%1], 0, 0x989680;\n\t"
                "selp.b32 %0, 1, 0, p;\n\t}"
                : "=r"(done) : "r"(mbar_addr) : "memory");
        }
    } else {
        for (int i = threadIdx.x; i < n_clusters; i += BLOCK_THREADS)
            srow[i] = xrow[i];
        __syncthreads();
    }

    float4* __restrict__ o = reinterpret_cast<float4*>(out + (size_t)b * n_vertices);
    const int S = BLOCK_THREADS;
    const int nv4 = n_vertices >> 2;           // 25000 (exact for 100000)

    if (use_u16) {
        // ---- Gather: 2x LDG.64 (u16 x4 idx) -> 8x LDS -> 2x STG.128.cs ----
        // Same thread->quad mapping as R5: quads v and v+S (coalesced stores).
        const uint2* __restrict__ idx4 = reinterpret_cast<const uint2*>(g_v2c16);

        int v = threadIdx.x;
        while (v + S < nv4) {
            const uint2 w0 = idx4[v];
            const uint2 w1 = idx4[v + S];
            float4 a0, a1;
            a0.x = srow[w0.x & 0xFFFF]; a0.y = srow[w0.x >> 16];
            a0.z = srow[w0.y & 0xFFFF]; a0.w = srow[w0.y >> 16];
            a1.x = srow[w1.x & 0xFFFF]; a1.y = srow[w1.x >> 16];
            a1.z = srow[w1.y & 0xFFFF]; a1.w = srow[w1.y >> 16];
            __stcs(&o[v],     a0);
            __stcs(&o[v + S], a1);
            v += 2 * S;
        }
        if (v < nv4) {
            const uint2 w = idx4[v];
            float4 a;
            a.x = srow[w.x & 0xFFFF]; a.y = srow[w.x >> 16];
            a.z = srow[w.y & 0xFFFF]; a.w = srow[w.y >> 16];
            __stcs(&o[v], a);
        }
        // scalar tail (dead for 100000, kept for safety)
        for (int t = (nv4 << 2) + threadIdx.x; t < n_vertices; t += S) {
            out[(size_t)b * n_vertices + t] = srow[v2c[t]];
        }
    } else {
        // fallback: int32 index path (exact R5)
        const int4* __restrict__ v2c4 = reinterpret_cast<const int4*>(v2c);
        int v = threadIdx.x;
        while (v + S < nv4) {
            const int4 c0 = v2c4[v];
            const int4 c1 = v2c4[v + S];
            float4 a0, a1;
            a0.x = srow[c0.x]; a0.y = srow[c0.y]; a0.z = srow[c0.z]; a0.w = srow[c0.w];
            a1.x = srow[c1.x]; a1.y = srow[c1.y]; a1.z = srow[c1.z]; a1.w = srow[c1.w];
            __stcs(&o[v],     a0);
            __stcs(&o[v + S], a1);
            v += 2 * S;
        }
        if (v < nv4) {
            const int4 c = v2c4[v];
            float4 a;
            a.x = srow[c.x]; a.y = srow[c.y]; a.z = srow[c.z]; a.w = srow[c.w];
            __stcs(&o[v], a);
        }
        for (int t = (nv4 << 2) + threadIdx.x; t < n_vertices; t += S) {
            out[(size_t)b * n_vertices + t] = srow[v2c[t]];
        }
    }
}

extern "C" void kernel_launch(void* const* d_in, const int* in_sizes, int n_in,
                              void* d_out, int out_size)
{
    const float* x   = (const float*)d_in[0];
    const int*   v2c = (const int*)  d_in[1];
    float*       out = (float*)d_out;

    const int n_vertices = in_sizes[1];                  // 100000
    const int batch      = out_size / n_vertices;        // 1024
    const int n_clusters = in_sizes[0] / batch;          // 25000

    const int row_bytes  = n_clusters * (int)sizeof(float);      // 100000
    const int smem_bytes = ((row_bytes + 15) & ~15) + 16;        // row + mbarrier

    static bool attr_set = false;
    if (!attr_set) {
        cudaFuncSetAttribute(graph_reverse_pool_kernel,
                             cudaFuncAttributeMaxDynamicSharedMemorySize,
                             smem_bytes);
        attr_set = true;
    }

    const int use_u16 = (n_clusters <= 65535) &&
                        (n_vertices <= MAX_VERTICES_U16) &&
                        ((n_vertices & 3) == 0);

    if (use_u16) {
        const int n8 = (n_vertices + 7) / 8;
        pack_v2c_kernel<<<(n8 + 255) / 256, 256>>>(v2c, n_vertices);
    }

    graph_reverse_pool_kernel<<<batch, BLOCK_THREADS, smem_bytes>>>(
        x, v2c, out, batch, n_clusters, n_vertices, use_u16 ? 1 : 0);
}